// round 16
// baseline (speedup 1.0000x reference)
#include <cuda_runtime.h>
#include <cuda_bf16.h>
#include <math.h>

#define Bb 256
#define Tt 15
#define Ll 6
#define Uu 1000
#define Ee 1024
#define Vv 32000
#define G3 3000
#define LDXP 18000   // L * 3U
#define EU 2024      // E + U (rows of kernels_rest)
#define KP_E 512     // E/2 pairs
#define KP_U 500     // U/2 pairs
#define KP_D 3000    // (L*U)/2 pairs

// ---------------- scratch (device globals; no allocation allowed) ----------
__device__ __align__(16) unsigned g_Embp[Tt*Bb*KP_E];          // [T*B][512]
__device__ __align__(16) unsigned g_Wxp[KP_E*LDXP];            // [512][18000]
__device__ __align__(16) unsigned g_Rp[Ll*KP_U*G3];            // [l][kp][3000]
__device__ __align__(16) unsigned g_Sp[(Ll-1)*KP_U*G3];        // [l-1][kp][3000]
__device__ __align__(16) unsigned g_Dp[(size_t)KP_D*Vv];       // [3000][32000]
__device__ __align__(16) unsigned g_HpT[(Tt+1)*Ll*Bb*KP_U];    // [t+1][l][b][jj]
__device__ __align__(16) float    g_HfT[(size_t)(Tt+1)*Ll*Bb*Uu]; // [t+1][l][b][u]
__device__ __align__(16) float    g_XP[(size_t)Tt*Bb*LDXP];    // [t][b][18000]
__device__ __align__(16) float    g_MH[(size_t)Ll*Bb*G3];      // rec results per stage
__device__ __align__(16) float    g_SK[(size_t)Ll*Bb*G3];      // skip results per stage

// ---------------- helpers ---------------------------------------------------
__device__ __forceinline__ unsigned packbf(float a, float b) {
    __nv_bfloat162 h = __floats2bfloat162_rn(a, b);
    return *reinterpret_cast<unsigned*>(&h);
}

__device__ __forceinline__ void mma_bf16(float c[4], const unsigned a[4], const unsigned b[2]) {
    asm volatile(
        "mma.sync.aligned.m16n8k16.row.col.f32.bf16.bf16.f32 "
        "{%0,%1,%2,%3}, {%4,%5,%6,%7}, {%8,%9}, {%0,%1,%2,%3};\n"
        : "+f"(c[0]), "+f"(c[1]), "+f"(c[2]), "+f"(c[3])
        : "r"(a[0]), "r"(a[1]), "r"(a[2]), "r"(a[3]), "r"(b[0]), "r"(b[1]));
}

__device__ __forceinline__ void cp16(void* dst, const void* src, bool valid) {
    unsigned s = (unsigned)__cvta_generic_to_shared(dst);
    asm volatile("cp.async.cg.shared.global [%0], [%1], 16, %2;\n"
                 :: "r"(s), "l"(src), "r"(valid ? 16 : 0));
}
#define CP_COMMIT() asm volatile("cp.async.commit_group;\n")
#define CP_WAIT1()  asm volatile("cp.async.wait_group 1;\n")
#define CP_WAIT0()  asm volatile("cp.async.wait_group 0;\n")

__device__ __forceinline__ float sigf(float x) { return 1.f / (1.f + __expf(-x)); }

// ================= proven 2-stage bf16 GEMM body + accum flag ===============
template<int BM, int BN, int WM, int WN>
__device__ __forceinline__ void gemm_bf16_body(
    const unsigned* __restrict__ Ap, int ldap,
    const unsigned* __restrict__ Bp, int ldbp,
    float* __restrict__ C, int ldc,
    const float* __restrict__ bias,
    int N, int KP, bool accum)
{
    constexpr int NTH = WM * WN * 32;
    constexpr int KPP = 20;
    constexpr int BNP = BN + 8;
    constexpr int MT  = BM / WM / 16;
    constexpr int NT  = BN / WN / 8;
    constexpr int ACH = (BM * 4) / NTH;
    constexpr int BCH = (16 * BN / 4) / NTH;
    constexpr int BN4 = BN / 4;

    __shared__ alignas(16) unsigned As[2][BM][KPP];
    __shared__ alignas(16) unsigned Bs[2][16][BNP];

    const int tid  = threadIdx.x;
    const int m0   = blockIdx.y * BM;
    const int n0   = blockIdx.x * BN;
    const int warp = tid >> 5, lane = tid & 31;
    const int gid  = lane >> 2, tig = lane & 3;
    const int wM   = (warp / WN) * (BM / WM);
    const int wN   = (warp % WN) * (BN / WN);

    float acc[MT][NT][4];
#pragma unroll
    for (int i = 0; i < MT; i++)
#pragma unroll
        for (int j = 0; j < NT; j++)
#pragma unroll
            for (int q = 0; q < 4; q++) acc[i][j][q] = 0.f;

    const int NC = (KP + 15) >> 4;

    auto issue = [&](int s) {
        const int kp0 = s * 16;
        const int buf = s & 1;
#pragma unroll
        for (int h = 0; h < ACH; h++) {
            int c = tid + h * NTH;
            int row = c >> 2, q = c & 3;
            bool v = (kp0 + q * 4) < KP;
            const unsigned* src = Ap + (size_t)(m0 + row) * ldap + (v ? (kp0 + q * 4) : 0);
            cp16(&As[buf][row][q * 4], src, v);
        }
#pragma unroll
        for (int h = 0; h < BCH; h++) {
            int c = tid + h * NTH;
            int kr = c / BN4, qn = c % BN4;
            bool v = ((kp0 + kr) < KP) && ((n0 + qn * 4) < N);
            const unsigned* src = Bp + (size_t)(v ? (kp0 + kr) : 0) * ldbp + (v ? (n0 + qn * 4) : 0);
            cp16(&Bs[buf][kr][qn * 4], src, v);
        }
        CP_COMMIT();
    };

    issue(0);
    for (int s = 0; s < NC; s++) {
        if (s + 1 < NC) { issue(s + 1); CP_WAIT1(); }
        else            { CP_WAIT0(); }
        __syncthreads();
        const int buf = s & 1;
#pragma unroll
        for (int ks = 0; ks < 2; ks++) {
            unsigned af[MT][4], bfr[NT][2];
#pragma unroll
            for (int i = 0; i < MT; i++) {
                int r = wM + i * 16 + gid;
                af[i][0] = As[buf][r    ][ks * 8 + tig];
                af[i][1] = As[buf][r + 8][ks * 8 + tig];
                af[i][2] = As[buf][r    ][ks * 8 + 4 + tig];
                af[i][3] = As[buf][r + 8][ks * 8 + 4 + tig];
            }
#pragma unroll
            for (int j = 0; j < NT; j++) {
                int cn = wN + j * 8 + gid;
                bfr[j][0] = Bs[buf][ks * 8 + tig    ][cn];
                bfr[j][1] = Bs[buf][ks * 8 + 4 + tig][cn];
            }
#pragma unroll
            for (int i = 0; i < MT; i++)
#pragma unroll
                for (int j = 0; j < NT; j++)
                    mma_bf16(acc[i][j], af[i], bfr[j]);
        }
        __syncthreads();
    }

#pragma unroll
    for (int i = 0; i < MT; i++) {
        int r0 = m0 + wM + i * 16 + gid;
        int r1 = r0 + 8;
#pragma unroll
        for (int j = 0; j < NT; j++) {
            int c = n0 + wN + j * 8 + 2 * tig;
            if (c < N) {
                float b0 = bias ? bias[c]     : 0.f;
                float b1 = bias ? bias[c + 1] : 0.f;
                float2* p0 = (float2*)(C + (size_t)r0 * ldc + c);
                float2* p1 = (float2*)(C + (size_t)r1 * ldc + c);
                float2 v0 = make_float2(acc[i][j][0] + b0, acc[i][j][1] + b1);
                float2 v1 = make_float2(acc[i][j][2] + b0, acc[i][j][3] + b1);
                if (accum) {
                    float2 o0 = *p0, o1 = *p1;
                    v0.x += o0.x; v0.y += o0.y;
                    v1.x += o1.x; v1.y += o1.y;
                }
                *p0 = v0; *p1 = v1;
            }
        }
    }
}

template<int BM, int BN, int WM, int WN>
__global__ void __launch_bounds__(WM*WN*32)
gemm_bf16_kernel(const unsigned* Ap, int ldap, const unsigned* Bp, int ldbp,
                 float* C, int ldc, const float* bias, int N, int KP, int accum) {
    gemm_bf16_body<BM, BN, WM, WN>(Ap, ldap, Bp, ldbp, C, ldc, bias, N, KP, accum != 0);
}

// ================= wavefront stage kernels (R14 proven: 64x128/256thr) ======
__global__ void __launch_bounds__(256)
stage_gemm_kernel(int s,
                  const unsigned* __restrict__ HpT,
                  const unsigned* __restrict__ Rp,
                  const unsigned* __restrict__ Sp,
                  float* __restrict__ MH, float* __restrict__ SK,
                  const float* __restrict__ bias_rec)
{
    int lmin = (s > Tt - 1) ? (s - (Tt - 1)) : 0;
    int job  = blockIdx.z;
    int l    = lmin + (job >> 1);
    int type = job & 1;
    int t    = s - l;
    if (type == 1 && l == 0) return;

    const unsigned* Ap;
    const unsigned* Bp;
    float* C;
    const float* bias;
    if (type == 0) {   // rec: A = h_l(t-1) = HpT slot t
        Ap   = HpT + (((size_t)t * Ll + l) * Bb) * KP_U;
        Bp   = Rp + (size_t)l * KP_U * G3;
        C    = MH + (size_t)l * Bb * G3;
        bias = bias_rec + l * G3;
    } else {           // skip: A = h_{l-1}(t) = HpT slot t+1
        Ap   = HpT + (((size_t)(t + 1) * Ll + (l - 1)) * Bb) * KP_U;
        Bp   = Sp + (size_t)(l - 1) * KP_U * G3;
        C    = SK + (size_t)l * Bb * G3;
        bias = nullptr;
    }
    gemm_bf16_body<64, 128, 2, 4>(Ap, KP_U, Bp, G3, C, G3, bias, G3, KP_U, false);
}

__global__ void __launch_bounds__(256)
stage_gate_kernel(int s,
                  const float* __restrict__ XP,
                  const float* __restrict__ MH,
                  const float* __restrict__ SK,
                  float* __restrict__ HfT,
                  unsigned* __restrict__ HpT)
{
    int lmin = (s > Tt - 1) ? (s - (Tt - 1)) : 0;
    int l = lmin + blockIdx.z;
    int t = s - l;
    int idx = blockIdx.x * 256 + threadIdx.x;
    if (idx >= Bb * KP_U) return;
    int b = idx / KP_U, jj = idx % KP_U;
    int j = 2 * jj;

    const float* xp = XP + ((size_t)t * Bb + b) * LDXP + l * G3;
    const float* mh = MH + ((size_t)l * Bb + b) * G3;
    const float* sk = SK + ((size_t)l * Bb + b) * G3;
    const float* ho = HfT + (((size_t)t * Ll + l) * Bb + b) * Uu;
    float*       hn = HfT + (((size_t)(t + 1) * Ll + l) * Bb + b) * Uu;
    unsigned*    hp = HpT + (((size_t)(t + 1) * Ll + l) * Bb + b) * KP_U;

    float2 xz = *(const float2*)(xp + j);
    float2 xr = *(const float2*)(xp + j + Uu);
    float2 xh = *(const float2*)(xp + j + 2 * Uu);
    if (l > 0) {
        float2 sz = *(const float2*)(sk + j);
        float2 sr = *(const float2*)(sk + j + Uu);
        float2 sh = *(const float2*)(sk + j + 2 * Uu);
        xz.x += sz.x; xz.y += sz.y;
        xr.x += sr.x; xr.y += sr.y;
        xh.x += sh.x; xh.y += sh.y;
    }
    float2 hz = *(const float2*)(mh + j);
    float2 hr = *(const float2*)(mh + j + Uu);
    float2 hh = *(const float2*)(mh + j + 2 * Uu);
    float2 hov = *(const float2*)(ho + j);

    float z0 = sigf(xz.x + hz.x), z1 = sigf(xz.y + hz.y);
    float r0 = sigf(xr.x + hr.x), r1 = sigf(xr.y + hr.y);
    float c0 = tanhf(xh.x + r0 * hh.x), c1 = tanhf(xh.y + r1 * hh.y);
    float h0 = z0 * hov.x + (1.f - z0) * c0;
    float h1 = z1 * hov.y + (1.f - z1) * c1;

    *(float2*)(hn + j) = make_float2(h0, h1);
    hp[jj] = packbf(h0, h1);
}

// ---------------- prep / pack kernels (float4-vectorized) -------------------
__global__ void embed_kernel(const int* __restrict__ tokens,
                             const float* __restrict__ table) {
    int m = blockIdx.x;              // m = t*B + b
    int t = m / Bb, b = m % Bb;
    int tok = tokens[b * Tt + t];
    float4 v = ((const float4*)(table + (size_t)tok * Ee))[threadIdx.x];
    *(uint2*)(g_Embp + (size_t)m * KP_E + threadIdx.x * 2) =
        make_uint2(packbf(v.x, v.y), packbf(v.z, v.w));
}

__global__ void packwx_kernel(const float* __restrict__ k0,
                              const float* __restrict__ krest) {
    int n4 = blockIdx.x * 256 + threadIdx.x;   // 0..4499
    int kp = blockIdx.y;
    if (n4 >= LDXP / 4) return;
    int l = n4 / 750, j = (n4 % 750) * 4;
    const float* base = (l == 0) ? k0 : (krest + (size_t)(l - 1) * EU * G3);
    float4 a = *(const float4*)(base + (size_t)(2 * kp) * G3 + j);
    float4 b = *(const float4*)(base + (size_t)(2 * kp + 1) * G3 + j);
    *(uint4*)(g_Wxp + (size_t)kp * LDXP + l * G3 + j) =
        make_uint4(packbf(a.x, b.x), packbf(a.y, b.y), packbf(a.z, b.z), packbf(a.w, b.w));
}

__global__ void packrec_kernel(const float* __restrict__ rec) {
    int n4 = blockIdx.x * 256 + threadIdx.x;   // 0..749
    if (n4 >= G3 / 4) return;
    int kp = blockIdx.y, l = blockIdx.z;
    const float* src = rec + (size_t)l * Uu * G3;
    float4 a = *(const float4*)(src + (size_t)(2 * kp) * G3 + 4 * n4);
    float4 b = *(const float4*)(src + (size_t)(2 * kp + 1) * G3 + 4 * n4);
    *(uint4*)(g_Rp + ((size_t)l * KP_U + kp) * G3 + 4 * n4) =
        make_uint4(packbf(a.x, b.x), packbf(a.y, b.y), packbf(a.z, b.z), packbf(a.w, b.w));
}

__global__ void packskip_kernel(const float* __restrict__ krest) {
    int n4 = blockIdx.x * 256 + threadIdx.x;
    if (n4 >= G3 / 4) return;
    int kp = blockIdx.y, l = blockIdx.z;        // l = 0..4
    const float* src = krest + (size_t)l * EU * G3 + (size_t)Ee * G3;
    float4 a = *(const float4*)(src + (size_t)(2 * kp) * G3 + 4 * n4);
    float4 b = *(const float4*)(src + (size_t)(2 * kp + 1) * G3 + 4 * n4);
    *(uint4*)(g_Sp + ((size_t)l * KP_U + kp) * G3 + 4 * n4) =
        make_uint4(packbf(a.x, b.x), packbf(a.y, b.y), packbf(a.z, b.z), packbf(a.w, b.w));
}

__global__ void packdense_kernel(const float* __restrict__ dk) {
    int n4 = blockIdx.x * 256 + threadIdx.x;   // 0..7999
    if (n4 >= Vv / 4) return;
    int kp = blockIdx.y;
    float4 a = *(const float4*)(dk + (size_t)(2 * kp) * Vv + 4 * n4);
    float4 b = *(const float4*)(dk + (size_t)(2 * kp + 1) * Vv + 4 * n4);
    *(uint4*)(g_Dp + (size_t)kp * Vv + 4 * n4) =
        make_uint4(packbf(a.x, b.x), packbf(a.y, b.y), packbf(a.z, b.z), packbf(a.w, b.w));
}

__global__ void inith_kernel(const float* __restrict__ init) {
    int idx = blockIdx.x * 256 + threadIdx.x;   // over Ll*Bb*KP_U
    if (idx >= Ll * Bb * KP_U) return;
    float2 v = *(const float2*)(init + 2 * (size_t)idx);   // layout matches [l][b][u]
    *(float2*)(g_HfT + 2 * (size_t)idx) = v;
    g_HpT[idx] = packbf(v.x, v.y);
}

// ---------------- row softmax in-place on d_out [256, 32000] ---------------
__global__ void softmax_kernel(float* __restrict__ out) {
    int row = blockIdx.x;
    float* p = out + (size_t)row * Vv;
    __shared__ float red[256];
    int tid = threadIdx.x;

    float m = -1e30f;
    for (int i = tid; i < Vv; i += 256) m = fmaxf(m, p[i]);
    red[tid] = m; __syncthreads();
    for (int s = 128; s > 0; s >>= 1) {
        if (tid < s) red[tid] = fmaxf(red[tid], red[tid + s]);
        __syncthreads();
    }
    m = red[0]; __syncthreads();

    float sum = 0.f;
    for (int i = tid; i < Vv; i += 256) {
        float e = expf(p[i] - m);
        p[i] = e;
        sum += e;
    }
    red[tid] = sum; __syncthreads();
    for (int s = 128; s > 0; s >>= 1) {
        if (tid < s) red[tid] += red[tid + s];
        __syncthreads();
    }
    float inv = 1.f / red[0];
    for (int i = tid; i < Vv; i += 256) p[i] *= inv;
}

// ---------------- persistent stream/event resources (created once) ----------
static bool         g_resOk = false;
static bool         g_resTried = false;
static cudaStream_t g_sX = 0, g_sD = 0;
static cudaEvent_t  g_evFork = 0, g_evEmb = 0;
static cudaEvent_t  g_evXP[Tt], g_evGateD[Ll], g_evDenseDone = 0;

static bool ensure_resources() {
    if (g_resTried) return g_resOk;
    g_resTried = true;
    bool ok = true;
    int loP = 0, hiP = 0;
    cudaDeviceGetStreamPriorityRange(&loP, &hiP);   // loP = least priority
    ok = ok && (cudaStreamCreateWithPriority(&g_sX, cudaStreamNonBlocking, loP) == cudaSuccess);
    ok = ok && (cudaStreamCreateWithPriority(&g_sD, cudaStreamNonBlocking, loP) == cudaSuccess);
    ok = ok && (cudaEventCreateWithFlags(&g_evFork, cudaEventDisableTiming) == cudaSuccess);
    ok = ok && (cudaEventCreateWithFlags(&g_evEmb, cudaEventDisableTiming) == cudaSuccess);
    for (int t = 0; t < Tt && ok; t++)
        ok = (cudaEventCreateWithFlags(&g_evXP[t], cudaEventDisableTiming) == cudaSuccess);
    for (int l = 0; l < Ll && ok; l++)
        ok = (cudaEventCreateWithFlags(&g_evGateD[l], cudaEventDisableTiming) == cudaSuccess);
    ok = ok && (cudaEventCreateWithFlags(&g_evDenseDone, cudaEventDisableTiming) == cudaSuccess);
    g_resOk = ok;
    return ok;
}

// ---------------- launch: forked-stream DAG with serial fallback ------------
extern "C" void kernel_launch(void* const* d_in, const int* in_sizes, int n_in,
                              void* d_out, int out_size) {
    const int*   tokens       = (const int*)  d_in[0];
    const float* init_states  = (const float*)d_in[1];
    const float* emb_table    = (const float*)d_in[2];
    const float* kernel0      = (const float*)d_in[3];
    const float* kernels_rest = (const float*)d_in[4];
    const float* rec_kernels  = (const float*)d_in[5];
    const float* bias_in      = (const float*)d_in[6];
    const float* bias_rec     = (const float*)d_in[7];
    const float* dense_kernel = (const float*)d_in[8];
    const float* dense_bias   = (const float*)d_in[9];
    float* out = (float*)d_out;

    unsigned *pEmbp, *pWxp, *pRp, *pSp, *pDp, *pHpT;
    float *pXP, *pMH, *pSK, *pHfT;
    cudaGetSymbolAddress((void**)&pEmbp, g_Embp);
    cudaGetSymbolAddress((void**)&pWxp,  g_Wxp);
    cudaGetSymbolAddress((void**)&pRp,   g_Rp);
    cudaGetSymbolAddress((void**)&pSp,   g_Sp);
    cudaGetSymbolAddress((void**)&pDp,   g_Dp);
    cudaGetSymbolAddress((void**)&pHpT,  g_HpT);
    cudaGetSymbolAddress((void**)&pXP,   g_XP);
    cudaGetSymbolAddress((void**)&pMH,   g_MH);
    cudaGetSymbolAddress((void**)&pSK,   g_SK);
    cudaGetSymbolAddress((void**)&pHfT,  g_HfT);

    bool ok = ensure_resources();

    // ---- shared prologue on stream 0 ----
    embed_kernel<<<Tt*Bb, 256>>>(tokens, emb_table);
    packwx_kernel<<<dim3((LDXP/4 + 255)/256, KP_E), 256>>>(kernel0, kernels_rest);

    if (ok) {
        // ======== forked-stream DAG path ========
        cudaEventRecord(g_evEmb, 0);          // XP inputs ready
        cudaEventRecord(g_evFork, 0);
        cudaStreamWaitEvent(g_sX, g_evEmb, 0);
        cudaStreamWaitEvent(g_sD, g_evFork, 0);

        // stream D (low prio): pack dense weights
        packdense_kernel<<<dim3((Vv/4 + 255)/256, KP_D), 256, 0, g_sD>>>(dense_kernel);

        // stream X (low prio): per-timestep XP projections (64x128 shape)
        for (int t = 0; t < Tt; t++) {
            gemm_bf16_kernel<64,128,2,4><<<dim3((LDXP+127)/128, Bb/64), 256, 0, g_sX>>>(
                pEmbp + (size_t)t * Bb * KP_E, KP_E, pWxp, LDXP,
                pXP + (size_t)t * Bb * LDXP, LDXP, bias_in, LDXP, KP_E, 0);
            cudaEventRecord(g_evXP[t], g_sX);
        }

        // main: remaining packs + init
        packrec_kernel<<<dim3((G3/4 + 255)/256, KP_U, Ll), 256>>>(rec_kernels);
        packskip_kernel<<<dim3((G3/4 + 255)/256, KP_U, Ll-1), 256>>>(kernels_rest);
        inith_kernel<<<(Ll*Bb*KP_U + 255)/256, 256>>>(init_states);

        // main: wavefront
        int lastWait = -1;
        for (int s = 0; s < Tt + Ll - 1; s++) {
            int lmin = (s > Tt - 1) ? (s - (Tt - 1)) : 0;
            int lmax = (s < Ll - 1) ? s : (Ll - 1);
            int ncells = lmax - lmin + 1;
            stage_gemm_kernel<<<dim3((G3+127)/128, Bb/64, ncells*2), 256>>>(
                s, pHpT, pRp, pSp, pMH, pSK, bias_rec);
            int tmax = (s < Tt - 1) ? s : (Tt - 1);
            if (tmax > lastWait) {
                cudaStreamWaitEvent(0, g_evXP[tmax], 0);
                lastWait = tmax;
            }
            stage_gate_kernel<<<dim3((Bb*KP_U + 255)/256, 1, ncells), 256>>>(
                s, pXP, pMH, pSK, pHfT, pHpT);
            if (s >= Tt - 1)
                cudaEventRecord(g_evGateD[s - (Tt - 1)], 0);
        }

        // stream D: dense k-partials, each gated on its layer's final state
        for (int l = 0; l < Ll; l++) {
            cudaStreamWaitEvent(g_sD, g_evGateD[l], 0);
            gemm_bf16_kernel<128,128,2,4><<<dim3(Vv/128, Bb/128), 256, 0, g_sD>>>(
                pHpT + (((size_t)Tt * Ll + l) * Bb) * KP_U, KP_U,
                pDp + (size_t)l * KP_U * Vv, Vv,
                out, Vv,
                (l == 0) ? dense_bias : nullptr, Vv, KP_U, l > 0 ? 1 : 0);
        }
        cudaEventRecord(g_evDenseDone, g_sD);

        cudaStreamWaitEvent(0, g_evDenseDone, 0);
        softmax_kernel<<<Bb, 256>>>(out);
    } else {
        // ======== serial fallback ========
        packrec_kernel<<<dim3((G3/4 + 255)/256, KP_U, Ll), 256>>>(rec_kernels);
        packskip_kernel<<<dim3((G3/4 + 255)/256, KP_U, Ll-1), 256>>>(kernels_rest);
        packdense_kernel<<<dim3((Vv/4 + 255)/256, KP_D), 256>>>(dense_kernel);
        inith_kernel<<<(Ll*Bb*KP_U + 255)/256, 256>>>(init_states);

        gemm_bf16_kernel<128,128,2,4><<<dim3((LDXP+127)/128, (Tt*Bb)/128), 256>>>(
            pEmbp, KP_E, pWxp, LDXP, pXP, LDXP, bias_in, LDXP, KP_E, 0);

        for (int s = 0; s < Tt + Ll - 1; s++) {
            int lmin = (s > Tt - 1) ? (s - (Tt - 1)) : 0;
            int lmax = (s < Ll - 1) ? s : (Ll - 1);
            int ncells = lmax - lmin + 1;
            stage_gemm_kernel<<<dim3((G3+127)/128, Bb/64, ncells*2), 256>>>(
                s, pHpT, pRp, pSp, pMH, pSK, bias_rec);
            stage_gate_kernel<<<dim3((Bb*KP_U + 255)/256, 1, ncells), 256>>>(
                s, pXP, pMH, pSK, pHfT, pHpT);
        }

        for (int l = 0; l < Ll; l++) {
            gemm_bf16_kernel<128,128,2,4><<<dim3(Vv/128, Bb/128), 256>>>(
                pHpT + (((size_t)Tt * Ll + l) * Bb) * KP_U, KP_U,
                pDp + (size_t)l * KP_U * Vv, Vv,
                out, Vv,
                (l == 0) ? dense_bias : nullptr, Vv, KP_U, l > 0 ? 1 : 0);
        }
        softmax_kernel<<<Bb, 256>>>(out);
    }
}

// round 17
// speedup vs baseline: 1.0304x; 1.0304x over previous
#include <cuda_runtime.h>
#include <cuda_bf16.h>
#include <math.h>

#define Bb 256
#define Tt 15
#define Ll 6
#define Uu 1000
#define Ee 1024
#define Vv 32000
#define G3 3000
#define LDXP 18000   // L * 3U
#define EU 2024      // E + U (rows of kernels_rest)
#define KP_E 512     // E/2 pairs
#define KP_U 500     // U/2 pairs
#define KP_D 3000    // (L*U)/2 pairs

// ---------------- scratch (device globals; no allocation allowed) ----------
__device__ __align__(16) unsigned g_Embp[Tt*Bb*KP_E];          // [T*B][512]
__device__ __align__(16) unsigned g_Wxp[KP_E*LDXP];            // [512][18000]
__device__ __align__(16) unsigned g_Rp[Ll*KP_U*G3];            // [l][kp][3000]
__device__ __align__(16) unsigned g_Sp[(Ll-1)*KP_U*G3];        // [l-1][kp][3000]
__device__ __align__(16) unsigned g_Dp[(size_t)KP_D*Vv];       // [3000][32000]
__device__ __align__(16) unsigned g_HpT[(Tt+1)*Ll*Bb*KP_U];    // [t+1][l][b][jj]
__device__ __align__(16) float    g_HfT[(size_t)(Tt+1)*Ll*Bb*Uu]; // [t+1][l][b][u]
__device__ __align__(16) float    g_XP[(size_t)Tt*Bb*LDXP];    // [t][b][18000]
__device__ __align__(16) float    g_MH[(size_t)Ll*Bb*G3];      // rec results per stage
__device__ __align__(16) float    g_SK[(size_t)Ll*Bb*G3];      // skip results per stage

// ---------------- helpers ---------------------------------------------------
__device__ __forceinline__ unsigned packbf(float a, float b) {
    __nv_bfloat162 h = __floats2bfloat162_rn(a, b);
    return *reinterpret_cast<unsigned*>(&h);
}

__device__ __forceinline__ void mma_bf16(float c[4], const unsigned a[4], const unsigned b[2]) {
    asm volatile(
        "mma.sync.aligned.m16n8k16.row.col.f32.bf16.bf16.f32 "
        "{%0,%1,%2,%3}, {%4,%5,%6,%7}, {%8,%9}, {%0,%1,%2,%3};\n"
        : "+f"(c[0]), "+f"(c[1]), "+f"(c[2]), "+f"(c[3])
        : "r"(a[0]), "r"(a[1]), "r"(a[2]), "r"(a[3]), "r"(b[0]), "r"(b[1]));
}

__device__ __forceinline__ void cp16(void* dst, const void* src, bool valid) {
    unsigned s = (unsigned)__cvta_generic_to_shared(dst);
    asm volatile("cp.async.cg.shared.global [%0], [%1], 16, %2;\n"
                 :: "r"(s), "l"(src), "r"(valid ? 16 : 0));
}
#define CP_COMMIT() asm volatile("cp.async.commit_group;\n")
#define CP_WAIT1()  asm volatile("cp.async.wait_group 1;\n")
#define CP_WAIT0()  asm volatile("cp.async.wait_group 0;\n")

__device__ __forceinline__ float sigf(float x) { return 1.f / (1.f + __expf(-x)); }

// ================= proven 2-stage bf16 GEMM body + accum flag ===============
template<int BM, int BN, int WM, int WN>
__device__ __forceinline__ void gemm_bf16_body(
    const unsigned* __restrict__ Ap, int ldap,
    const unsigned* __restrict__ Bp, int ldbp,
    float* __restrict__ C, int ldc,
    const float* __restrict__ bias,
    int N, int KP, bool accum)
{
    constexpr int NTH = WM * WN * 32;
    constexpr int KPP = 20;
    constexpr int BNP = BN + 8;
    constexpr int MT  = BM / WM / 16;
    constexpr int NT  = BN / WN / 8;
    constexpr int ACH = (BM * 4) / NTH;
    constexpr int BCH = (16 * BN / 4) / NTH;
    constexpr int BN4 = BN / 4;

    __shared__ alignas(16) unsigned As[2][BM][KPP];
    __shared__ alignas(16) unsigned Bs[2][16][BNP];

    const int tid  = threadIdx.x;
    const int m0   = blockIdx.y * BM;
    const int n0   = blockIdx.x * BN;
    const int warp = tid >> 5, lane = tid & 31;
    const int gid  = lane >> 2, tig = lane & 3;
    const int wM   = (warp / WN) * (BM / WM);
    const int wN   = (warp % WN) * (BN / WN);

    float acc[MT][NT][4];
#pragma unroll
    for (int i = 0; i < MT; i++)
#pragma unroll
        for (int j = 0; j < NT; j++)
#pragma unroll
            for (int q = 0; q < 4; q++) acc[i][j][q] = 0.f;

    const int NC = (KP + 15) >> 4;

    auto issue = [&](int s) {
        const int kp0 = s * 16;
        const int buf = s & 1;
#pragma unroll
        for (int h = 0; h < ACH; h++) {
            int c = tid + h * NTH;
            int row = c >> 2, q = c & 3;
            bool v = (kp0 + q * 4) < KP;
            const unsigned* src = Ap + (size_t)(m0 + row) * ldap + (v ? (kp0 + q * 4) : 0);
            cp16(&As[buf][row][q * 4], src, v);
        }
#pragma unroll
        for (int h = 0; h < BCH; h++) {
            int c = tid + h * NTH;
            int kr = c / BN4, qn = c % BN4;
            bool v = ((kp0 + kr) < KP) && ((n0 + qn * 4) < N);
            const unsigned* src = Bp + (size_t)(v ? (kp0 + kr) : 0) * ldbp + (v ? (n0 + qn * 4) : 0);
            cp16(&Bs[buf][kr][qn * 4], src, v);
        }
        CP_COMMIT();
    };

    issue(0);
    for (int s = 0; s < NC; s++) {
        if (s + 1 < NC) { issue(s + 1); CP_WAIT1(); }
        else            { CP_WAIT0(); }
        __syncthreads();
        const int buf = s & 1;
#pragma unroll
        for (int ks = 0; ks < 2; ks++) {
            unsigned af[MT][4], bfr[NT][2];
#pragma unroll
            for (int i = 0; i < MT; i++) {
                int r = wM + i * 16 + gid;
                af[i][0] = As[buf][r    ][ks * 8 + tig];
                af[i][1] = As[buf][r + 8][ks * 8 + tig];
                af[i][2] = As[buf][r    ][ks * 8 + 4 + tig];
                af[i][3] = As[buf][r + 8][ks * 8 + 4 + tig];
            }
#pragma unroll
            for (int j = 0; j < NT; j++) {
                int cn = wN + j * 8 + gid;
                bfr[j][0] = Bs[buf][ks * 8 + tig    ][cn];
                bfr[j][1] = Bs[buf][ks * 8 + 4 + tig][cn];
            }
#pragma unroll
            for (int i = 0; i < MT; i++)
#pragma unroll
                for (int j = 0; j < NT; j++)
                    mma_bf16(acc[i][j], af[i], bfr[j]);
        }
        __syncthreads();
    }

#pragma unroll
    for (int i = 0; i < MT; i++) {
        int r0 = m0 + wM + i * 16 + gid;
        int r1 = r0 + 8;
#pragma unroll
        for (int j = 0; j < NT; j++) {
            int c = n0 + wN + j * 8 + 2 * tig;
            if (c < N) {
                float b0 = bias ? bias[c]     : 0.f;
                float b1 = bias ? bias[c + 1] : 0.f;
                float2* p0 = (float2*)(C + (size_t)r0 * ldc + c);
                float2* p1 = (float2*)(C + (size_t)r1 * ldc + c);
                float2 v0 = make_float2(acc[i][j][0] + b0, acc[i][j][1] + b1);
                float2 v1 = make_float2(acc[i][j][2] + b0, acc[i][j][3] + b1);
                if (accum) {
                    float2 o0 = *p0, o1 = *p1;
                    v0.x += o0.x; v0.y += o0.y;
                    v1.x += o1.x; v1.y += o1.y;
                }
                *p0 = v0; *p1 = v1;
            }
        }
    }
}

template<int BM, int BN, int WM, int WN>
__global__ void __launch_bounds__(WM*WN*32)
gemm_bf16_kernel(const unsigned* Ap, int ldap, const unsigned* Bp, int ldbp,
                 float* C, int ldc, const float* bias, int N, int KP, int accum) {
    gemm_bf16_body<BM, BN, WM, WN>(Ap, ldap, Bp, ldbp, C, ldc, bias, N, KP, accum != 0);
}

// ================= wavefront stage kernels (R14 proven: 64x128/256thr) ======
__global__ void __launch_bounds__(256)
stage_gemm_kernel(int s,
                  const unsigned* __restrict__ HpT,
                  const unsigned* __restrict__ Rp,
                  const unsigned* __restrict__ Sp,
                  float* __restrict__ MH, float* __restrict__ SK,
                  const float* __restrict__ bias_rec)
{
    int lmin = (s > Tt - 1) ? (s - (Tt - 1)) : 0;
    int job  = blockIdx.z;
    int l    = lmin + (job >> 1);
    int type = job & 1;
    int t    = s - l;
    if (type == 1 && l == 0) return;

    const unsigned* Ap;
    const unsigned* Bp;
    float* C;
    const float* bias;
    if (type == 0) {   // rec: A = h_l(t-1) = HpT slot t
        Ap   = HpT + (((size_t)t * Ll + l) * Bb) * KP_U;
        Bp   = Rp + (size_t)l * KP_U * G3;
        C    = MH + (size_t)l * Bb * G3;
        bias = bias_rec + l * G3;
    } else {           // skip: A = h_{l-1}(t) = HpT slot t+1
        Ap   = HpT + (((size_t)(t + 1) * Ll + (l - 1)) * Bb) * KP_U;
        Bp   = Sp + (size_t)(l - 1) * KP_U * G3;
        C    = SK + (size_t)l * Bb * G3;
        bias = nullptr;
    }
    gemm_bf16_body<64, 128, 2, 4>(Ap, KP_U, Bp, G3, C, G3, bias, G3, KP_U, false);
}

__global__ void __launch_bounds__(256)
stage_gate_kernel(int s,
                  const float* __restrict__ XP,
                  const float* __restrict__ MH,
                  const float* __restrict__ SK,
                  float* __restrict__ HfT,
                  unsigned* __restrict__ HpT)
{
    int lmin = (s > Tt - 1) ? (s - (Tt - 1)) : 0;
    int l = lmin + blockIdx.z;
    int t = s - l;
    int idx = blockIdx.x * 256 + threadIdx.x;
    if (idx >= Bb * KP_U) return;
    int b = idx / KP_U, jj = idx % KP_U;
    int j = 2 * jj;

    const float* xp = XP + ((size_t)t * Bb + b) * LDXP + l * G3;
    const float* mh = MH + ((size_t)l * Bb + b) * G3;
    const float* sk = SK + ((size_t)l * Bb + b) * G3;
    const float* ho = HfT + (((size_t)t * Ll + l) * Bb + b) * Uu;
    float*       hn = HfT + (((size_t)(t + 1) * Ll + l) * Bb + b) * Uu;
    unsigned*    hp = HpT + (((size_t)(t + 1) * Ll + l) * Bb + b) * KP_U;

    float2 xz = *(const float2*)(xp + j);
    float2 xr = *(const float2*)(xp + j + Uu);
    float2 xh = *(const float2*)(xp + j + 2 * Uu);
    if (l > 0) {
        float2 sz = *(const float2*)(sk + j);
        float2 sr = *(const float2*)(sk + j + Uu);
        float2 sh = *(const float2*)(sk + j + 2 * Uu);
        xz.x += sz.x; xz.y += sz.y;
        xr.x += sr.x; xr.y += sr.y;
        xh.x += sh.x; xh.y += sh.y;
    }
    float2 hz = *(const float2*)(mh + j);
    float2 hr = *(const float2*)(mh + j + Uu);
    float2 hh = *(const float2*)(mh + j + 2 * Uu);
    float2 hov = *(const float2*)(ho + j);

    float z0 = sigf(xz.x + hz.x), z1 = sigf(xz.y + hz.y);
    float r0 = sigf(xr.x + hr.x), r1 = sigf(xr.y + hr.y);
    float c0 = tanhf(xh.x + r0 * hh.x), c1 = tanhf(xh.y + r1 * hh.y);
    float h0 = z0 * hov.x + (1.f - z0) * c0;
    float h1 = z1 * hov.y + (1.f - z1) * c1;

    *(float2*)(hn + j) = make_float2(h0, h1);
    hp[jj] = packbf(h0, h1);
}

// ---------------- prep / pack kernels (float4-vectorized) -------------------
__global__ void embed_kernel(const int* __restrict__ tokens,
                             const float* __restrict__ table) {
    int m = blockIdx.x;              // m = t*B + b
    int t = m / Bb, b = m % Bb;
    int tok = tokens[b * Tt + t];
    float4 v = ((const float4*)(table + (size_t)tok * Ee))[threadIdx.x];
    *(uint2*)(g_Embp + (size_t)m * KP_E + threadIdx.x * 2) =
        make_uint2(packbf(v.x, v.y), packbf(v.z, v.w));
}

__global__ void packwx_kernel(const float* __restrict__ k0,
                              const float* __restrict__ krest) {
    int n4 = blockIdx.x * 256 + threadIdx.x;   // 0..4499
    int kp = blockIdx.y;
    if (n4 >= LDXP / 4) return;
    int l = n4 / 750, j = (n4 % 750) * 4;
    const float* base = (l == 0) ? k0 : (krest + (size_t)(l - 1) * EU * G3);
    float4 a = *(const float4*)(base + (size_t)(2 * kp) * G3 + j);
    float4 b = *(const float4*)(base + (size_t)(2 * kp + 1) * G3 + j);
    *(uint4*)(g_Wxp + (size_t)kp * LDXP + l * G3 + j) =
        make_uint4(packbf(a.x, b.x), packbf(a.y, b.y), packbf(a.z, b.z), packbf(a.w, b.w));
}

__global__ void packrec_kernel(const float* __restrict__ rec) {
    int n4 = blockIdx.x * 256 + threadIdx.x;   // 0..749
    if (n4 >= G3 / 4) return;
    int kp = blockIdx.y, l = blockIdx.z;
    const float* src = rec + (size_t)l * Uu * G3;
    float4 a = *(const float4*)(src + (size_t)(2 * kp) * G3 + 4 * n4);
    float4 b = *(const float4*)(src + (size_t)(2 * kp + 1) * G3 + 4 * n4);
    *(uint4*)(g_Rp + ((size_t)l * KP_U + kp) * G3 + 4 * n4) =
        make_uint4(packbf(a.x, b.x), packbf(a.y, b.y), packbf(a.z, b.z), packbf(a.w, b.w));
}

__global__ void packskip_kernel(const float* __restrict__ krest) {
    int n4 = blockIdx.x * 256 + threadIdx.x;
    if (n4 >= G3 / 4) return;
    int kp = blockIdx.y, l = blockIdx.z;        // l = 0..4
    const float* src = krest + (size_t)l * EU * G3 + (size_t)Ee * G3;
    float4 a = *(const float4*)(src + (size_t)(2 * kp) * G3 + 4 * n4);
    float4 b = *(const float4*)(src + (size_t)(2 * kp + 1) * G3 + 4 * n4);
    *(uint4*)(g_Sp + ((size_t)l * KP_U + kp) * G3 + 4 * n4) =
        make_uint4(packbf(a.x, b.x), packbf(a.y, b.y), packbf(a.z, b.z), packbf(a.w, b.w));
}

__global__ void packdense_kernel(const float* __restrict__ dk) {
    int n4 = blockIdx.x * 256 + threadIdx.x;   // 0..7999
    if (n4 >= Vv / 4) return;
    int kp = blockIdx.y;
    float4 a = *(const float4*)(dk + (size_t)(2 * kp) * Vv + 4 * n4);
    float4 b = *(const float4*)(dk + (size_t)(2 * kp + 1) * Vv + 4 * n4);
    *(uint4*)(g_Dp + (size_t)kp * Vv + 4 * n4) =
        make_uint4(packbf(a.x, b.x), packbf(a.y, b.y), packbf(a.z, b.z), packbf(a.w, b.w));
}

__global__ void inith_kernel(const float* __restrict__ init) {
    int idx = blockIdx.x * 256 + threadIdx.x;   // over Ll*Bb*KP_U
    if (idx >= Ll * Bb * KP_U) return;
    float2 v = *(const float2*)(init + 2 * (size_t)idx);   // layout matches [l][b][u]
    *(float2*)(g_HfT + 2 * (size_t)idx) = v;
    g_HpT[idx] = packbf(v.x, v.y);
}

// ---------------- row softmax in-place on d_out [256, 32000] ---------------
__global__ void softmax_kernel(float* __restrict__ out) {
    int row = blockIdx.x;
    float* p = out + (size_t)row * Vv;
    __shared__ float red[256];
    int tid = threadIdx.x;

    float m = -1e30f;
    for (int i = tid; i < Vv; i += 256) m = fmaxf(m, p[i]);
    red[tid] = m; __syncthreads();
    for (int s = 128; s > 0; s >>= 1) {
        if (tid < s) red[tid] = fmaxf(red[tid], red[tid + s]);
        __syncthreads();
    }
    m = red[0]; __syncthreads();

    float sum = 0.f;
    for (int i = tid; i < Vv; i += 256) {
        float e = expf(p[i] - m);
        p[i] = e;
        sum += e;
    }
    red[tid] = sum; __syncthreads();
    for (int s = 128; s > 0; s >>= 1) {
        if (tid < s) red[tid] += red[tid + s];
        __syncthreads();
    }
    float inv = 1.f / red[0];
    for (int i = tid; i < Vv; i += 256) p[i] *= inv;
}

// ---------------- persistent stream/event resources (created once) ----------
static bool         g_resOk = false;
static bool         g_resTried = false;
static cudaStream_t g_sX = 0, g_sD = 0;
static cudaEvent_t  g_evFork = 0, g_evEmb = 0, g_evPacks = 0;
static cudaEvent_t  g_evXP[Tt], g_evGateD[Ll], g_evDenseDone = 0;

static bool ensure_resources() {
    if (g_resTried) return g_resOk;
    g_resTried = true;
    bool ok = true;
    int loP = 0, hiP = 0;
    cudaDeviceGetStreamPriorityRange(&loP, &hiP);   // loP = least priority
    ok = ok && (cudaStreamCreateWithPriority(&g_sX, cudaStreamNonBlocking, loP) == cudaSuccess);
    ok = ok && (cudaStreamCreateWithPriority(&g_sD, cudaStreamNonBlocking, loP) == cudaSuccess);
    ok = ok && (cudaEventCreateWithFlags(&g_evFork, cudaEventDisableTiming) == cudaSuccess);
    ok = ok && (cudaEventCreateWithFlags(&g_evEmb, cudaEventDisableTiming) == cudaSuccess);
    ok = ok && (cudaEventCreateWithFlags(&g_evPacks, cudaEventDisableTiming) == cudaSuccess);
    for (int t = 0; t < Tt && ok; t++)
        ok = (cudaEventCreateWithFlags(&g_evXP[t], cudaEventDisableTiming) == cudaSuccess);
    for (int l = 0; l < Ll && ok; l++)
        ok = (cudaEventCreateWithFlags(&g_evGateD[l], cudaEventDisableTiming) == cudaSuccess);
    ok = ok && (cudaEventCreateWithFlags(&g_evDenseDone, cudaEventDisableTiming) == cudaSuccess);
    g_resOk = ok;
    return ok;
}

// ---------------- launch: forked-stream DAG with serial fallback ------------
extern "C" void kernel_launch(void* const* d_in, const int* in_sizes, int n_in,
                              void* d_out, int out_size) {
    const int*   tokens       = (const int*)  d_in[0];
    const float* init_states  = (const float*)d_in[1];
    const float* emb_table    = (const float*)d_in[2];
    const float* kernel0      = (const float*)d_in[3];
    const float* kernels_rest = (const float*)d_in[4];
    const float* rec_kernels  = (const float*)d_in[5];
    const float* bias_in      = (const float*)d_in[6];
    const float* bias_rec     = (const float*)d_in[7];
    const float* dense_kernel = (const float*)d_in[8];
    const float* dense_bias   = (const float*)d_in[9];
    float* out = (float*)d_out;

    unsigned *pEmbp, *pWxp, *pRp, *pSp, *pDp, *pHpT;
    float *pXP, *pMH, *pSK, *pHfT;
    cudaGetSymbolAddress((void**)&pEmbp, g_Embp);
    cudaGetSymbolAddress((void**)&pWxp,  g_Wxp);
    cudaGetSymbolAddress((void**)&pRp,   g_Rp);
    cudaGetSymbolAddress((void**)&pSp,   g_Sp);
    cudaGetSymbolAddress((void**)&pDp,   g_Dp);
    cudaGetSymbolAddress((void**)&pHpT,  g_HpT);
    cudaGetSymbolAddress((void**)&pXP,   g_XP);
    cudaGetSymbolAddress((void**)&pMH,   g_MH);
    cudaGetSymbolAddress((void**)&pSK,   g_SK);
    cudaGetSymbolAddress((void**)&pHfT,  g_HfT);

    bool ok = ensure_resources();

    if (ok) {
        // ======== forked-stream DAG path ========
        // fork sD immediately: small packs (stage-0 prerequisites) then dense pack
        cudaEventRecord(g_evFork, 0);
        cudaStreamWaitEvent(g_sD, g_evFork, 0);
        packrec_kernel<<<dim3((G3/4 + 255)/256, KP_U, Ll), 256, 0, g_sD>>>(rec_kernels);
        packskip_kernel<<<dim3((G3/4 + 255)/256, KP_U, Ll-1), 256, 0, g_sD>>>(kernels_rest);
        inith_kernel<<<(Ll*Bb*KP_U + 255)/256, 256, 0, g_sD>>>(init_states);
        cudaEventRecord(g_evPacks, g_sD);
        packdense_kernel<<<dim3((Vv/4 + 255)/256, KP_D), 256, 0, g_sD>>>(dense_kernel);

        // main: embed + packwx (XP prerequisites)
        embed_kernel<<<Tt*Bb, 256>>>(tokens, emb_table);
        packwx_kernel<<<dim3((LDXP/4 + 255)/256, KP_E), 256>>>(kernel0, kernels_rest);
        cudaEventRecord(g_evEmb, 0);

        // stream X (low prio): per-timestep XP projections (128x128 proven)
        cudaStreamWaitEvent(g_sX, g_evEmb, 0);
        for (int t = 0; t < Tt; t++) {
            gemm_bf16_kernel<128,128,2,4><<<dim3((LDXP+127)/128, Bb/128), 256, 0, g_sX>>>(
                pEmbp + (size_t)t * Bb * KP_E, KP_E, pWxp, LDXP,
                pXP + (size_t)t * Bb * LDXP, LDXP, bias_in, LDXP, KP_E, 0);
            cudaEventRecord(g_evXP[t], g_sX);
        }

        // main: wavefront (waits for the small packs once)
        cudaStreamWaitEvent(0, g_evPacks, 0);
        int lastWait = -1;
        for (int s = 0; s < Tt + Ll - 1; s++) {
            int lmin = (s > Tt - 1) ? (s - (Tt - 1)) : 0;
            int lmax = (s < Ll - 1) ? s : (Ll - 1);
            int ncells = lmax - lmin + 1;
            stage_gemm_kernel<<<dim3((G3+127)/128, Bb/64, ncells*2), 256>>>(
                s, pHpT, pRp, pSp, pMH, pSK, bias_rec);
            int tmax = (s < Tt - 1) ? s : (Tt - 1);
            if (tmax > lastWait) {
                cudaStreamWaitEvent(0, g_evXP[tmax], 0);
                lastWait = tmax;
            }
            stage_gate_kernel<<<dim3((Bb*KP_U + 255)/256, 1, ncells), 256>>>(
                s, pXP, pMH, pSK, pHfT, pHpT);
            if (s >= Tt - 1)
                cudaEventRecord(g_evGateD[s - (Tt - 1)], 0);
        }

        // stream D: dense k-partials, each gated on its layer's final state
        for (int l = 0; l < Ll; l++) {
            cudaStreamWaitEvent(g_sD, g_evGateD[l], 0);
            gemm_bf16_kernel<128,128,2,4><<<dim3(Vv/128, Bb/128), 256, 0, g_sD>>>(
                pHpT + (((size_t)Tt * Ll + l) * Bb) * KP_U, KP_U,
                pDp + (size_t)l * KP_U * Vv, Vv,
                out, Vv,
                (l == 0) ? dense_bias : nullptr, Vv, KP_U, l > 0 ? 1 : 0);
        }
        cudaEventRecord(g_evDenseDone, g_sD);

        cudaStreamWaitEvent(0, g_evDenseDone, 0);
        softmax_kernel<<<Bb, 256>>>(out);
    } else {
        // ======== serial fallback ========
        embed_kernel<<<Tt*Bb, 256>>>(tokens, emb_table);
        packwx_kernel<<<dim3((LDXP/4 + 255)/256, KP_E), 256>>>(kernel0, kernels_rest);
        packrec_kernel<<<dim3((G3/4 + 255)/256, KP_U, Ll), 256>>>(rec_kernels);
        packskip_kernel<<<dim3((G3/4 + 255)/256, KP_U, Ll-1), 256>>>(kernels_rest);
        packdense_kernel<<<dim3((Vv/4 + 255)/256, KP_D), 256>>>(dense_kernel);
        inith_kernel<<<(Ll*Bb*KP_U + 255)/256, 256>>>(init_states);

        gemm_bf16_kernel<128,128,2,4><<<dim3((LDXP+127)/128, (Tt*Bb)/128), 256>>>(
            pEmbp, KP_E, pWxp, LDXP, pXP, LDXP, bias_in, LDXP, KP_E, 0);

        for (int s = 0; s < Tt + Ll - 1; s++) {
            int lmin = (s > Tt - 1) ? (s - (Tt - 1)) : 0;
            int lmax = (s < Ll - 1) ? s : (Ll - 1);
            int ncells = lmax - lmin + 1;
            stage_gemm_kernel<<<dim3((G3+127)/128, Bb/64, ncells*2), 256>>>(
                s, pHpT, pRp, pSp, pMH, pSK, bias_rec);
            stage_gate_kernel<<<dim3((Bb*KP_U + 255)/256, 1, ncells), 256>>>(
                s, pXP, pMH, pSK, pHfT, pHpT);
        }

        for (int l = 0; l < Ll; l++) {
            gemm_bf16_kernel<128,128,2,4><<<dim3(Vv/128, Bb/128), 256>>>(
                pHpT + (((size_t)Tt * Ll + l) * Bb) * KP_U, KP_U,
                pDp + (size_t)l * KP_U * Vv, Vv,
                out, Vv,
                (l == 0) ? dense_bias : nullptr, Vv, KP_U, l > 0 ? 1 : 0);
        }
        softmax_kernel<<<Bb, 256>>>(out);
    }
}